// round 16
// baseline (speedup 1.0000x reference)
#include <cuda_runtime.h>
#include <cuda_fp16.h>
#include <cstdint>
#include <cstddef>

// Problem constants
#define B_     16
#define C_     256
#define HID    128
#define NH     4
#define DH     32
#define NP     4096       // 64*64 spatial positions
#define QKV_CH 384

// Scratch (device globals: allocation-free rule)
__device__ float  g_qkv[(size_t)B_ * HID * NP];      // q only, fp32 (33MB)
__device__ float  g_ctxp[4 * 64 * 1024];
__device__ __half g_wh [(size_t)QKV_CH * 256];       // w_qkv fp16 (single-term)
__device__ __half g_woh[(size_t)C_ * 128];           // w_out fp16 (single-term)
__device__ __half g_kh [(size_t)B_ * HID * NP];      // k fp16 (17MB)
__device__ __half g_keh[(size_t)B_ * HID * NP];      // softmax_n(k) fp16 (17MB)
__device__ __half g_vh [(size_t)B_ * HID * NP];      // v/4096 fp16 (17MB)

// ---------------------------------------------------------------------------
// Portable PTX helpers (sm_80+ only — harness lowers via compute_103 (non-'a'))
// ---------------------------------------------------------------------------
__device__ __forceinline__ uint32_t smem_u32(const void* p) {
    uint32_t a;
    asm("{ .reg .u64 t; cvta.to.shared.u64 t, %1; cvt.u32.u64 %0, t; }" : "=r"(a) : "l"(p));
    return a;
}
__device__ __forceinline__ void cp16(uint32_t s, const void* g) {
    asm volatile("cp.async.cg.shared.global [%0], [%1], 16;" :: "r"(s), "l"(g));
}
__device__ __forceinline__ void cp_commit() {
    asm volatile("cp.async.commit_group;" ::: "memory");
}
__device__ __forceinline__ void cp_wait1() {
    asm volatile("cp.async.wait_group 1;" ::: "memory");
}
__device__ __forceinline__ void cp_wait0() {
    asm volatile("cp.async.wait_group 0;" ::: "memory");
}
__device__ __forceinline__ void ldmatrix_x4(uint32_t& r0, uint32_t& r1,
                                            uint32_t& r2, uint32_t& r3, uint32_t addr) {
    asm volatile("ldmatrix.sync.aligned.m8n8.x4.shared.b16 {%0,%1,%2,%3}, [%4];"
                 : "=r"(r0), "=r"(r1), "=r"(r2), "=r"(r3) : "r"(addr));
}
__device__ __forceinline__ void mma_f16(float* d, const uint32_t* a, const uint32_t* b) {
    asm volatile(
        "mma.sync.aligned.m16n8k16.row.col.f32.f16.f16.f32 "
        "{%0,%1,%2,%3}, {%4,%5,%6,%7}, {%8,%9}, {%0,%1,%2,%3};"
        : "+f"(d[0]), "+f"(d[1]), "+f"(d[2]), "+f"(d[3])
        : "r"(a[0]), "r"(a[1]), "r"(a[2]), "r"(a[3]), "r"(b[0]), "r"(b[1]));
}

// ---------------------------------------------------------------------------
// K0: weight conversions only (x is now converted inside k_qkv_mma).
// blocks [0,384): w_qkv.  blocks [384,512): w_out.
// ---------------------------------------------------------------------------
__global__ __launch_bounds__(256) void k_conv_w(
    const float* __restrict__ wq, const float* __restrict__ wo)
{
    const int t = threadIdx.x;
    if (blockIdx.x < 384) {
        const int i = blockIdx.x * 256 + t;      // < 98304
        g_wh[i] = __float2half(wq[i]);
    } else {
        const int i = (blockIdx.x - 384) * 256 + t;   // < 32768
        g_woh[i] = __float2half(wo[i]);
    }
}

// ---------------------------------------------------------------------------
// K1: qkv GEMM with IN-KERNEL x conversion (overlaps the 167MB x stream with
// the HMMA work — conv_x kernel eliminated).
// Phase 0: per CTA, transpose-convert its B tile x[b][0:256][n0:n0+128]
//          fp32 -> fp16 into a FULLY-RESIDENT B smem buffer (128 rows x 528B;
//          row = position p, 256 contiguous c halfs + 16B pad).
// Phase 1: unchanged single-term fp16 mainloop; A (w) pipelined via 3-stage
//          cp.async ring; B fragments read from resident smem with kslot
//          column indexing (pattern validated in k_attn_out).
// blockIdx.y: 0=q (fp32 out), 1=k (fp16), 2=v (fp16 * 1/4096).
// smem: [0,30720) A ring (reused as fp32 staging in phase 0); [30720,98304) B.
// ---------------------------------------------------------------------------
__global__ __launch_bounds__(256) void k_qkv_mma(const float* __restrict__ x)
{
    __shared__ alignas(128) char S[98304];
    const uint32_t aBase = smem_u32(S);          // A ring (and phase-0 staging)
    const uint32_t bBase = aBase + 30720;        // resident B: 128 x 528B
    float* stg = (float*)S;                      // staging [32][132] fp32

    const int tid  = threadIdx.x;
    const int wid  = tid >> 5, lane = tid & 31;
    const int n0 = blockIdx.x * 128;
    const int my = blockIdx.y;
    const int b  = blockIdx.z;
    const int warp_m = wid >> 1, warp_n = wid & 1;

    // ---- Phase 0: convert B tile (8 rounds of 32 channels) ----
    {
        const float* xb = x + (size_t)b * C_ * NP + n0;
        const int l_row = tid >> 5;          // staging loader: c-row 0..7 (+8 step)
        const int l_ch  = tid & 31;          // 16B chunk along p
        const int p  = tid >> 1;             // converter: position 0..127
        const int ch = (tid & 1) * 16;       // 16-channel half
        for (int r = 0; r < 8; r++) {
            const int c0 = r * 32;
            #pragma unroll
            for (int i = 0; i < 4; i++) {
                const int row = l_row + i * 8;
                cp16(aBase + (uint32_t)row * 528 + l_ch * 16,
                     xb + (size_t)(c0 + row) * NP + l_ch * 4);
            }
            cp_commit();
            cp_wait0();
            __syncthreads();
            union { __half h[16]; uint4 u[2]; } hb;
            #pragma unroll
            for (int j = 0; j < 16; j++)
                hb.h[j] = __float2half(stg[(ch + j) * 132 + p]);
            uint4* dst = (uint4*)(S + 30720 + (uint32_t)p * 528 + c0 * 2 + ch * 2);
            dst[0] = hb.u[0];
            dst[1] = hb.u[1];
            __syncthreads();    // staging free for next round
        }
    }

    // ---- Phase 1: GEMM ----
    const __half* __restrict__ Ag = g_wh + (size_t)my * 128 * 256;
    const uint32_t ABUF = 128 * 80;

    uint32_t lso[2]; uint32_t lgi[2];
    #pragma unroll
    for (int i = 0; i < 2; i++) {
        const int slot = tid + i * 256;
        const int r = slot >> 2, ch = slot & 3;
        lso[i] = (uint32_t)r * 80 + ch * 16;
        lgi[i] = (uint32_t)r * 256 + ch * 8;
    }

    const int aRowL = warp_m * 32 + (lane & 15);
    const uint32_t aCol16 = (uint32_t)(lane >> 4) * 16;
    const int bg = lane >> 3, blr = lane & 7;
    const int bRowL = warp_n * 64 + (bg >> 1) * 8 + blr;
    const uint32_t bCol16 = (uint32_t)(bg & 1) * 16;

    float d[2][8][4];
    #pragma unroll
    for (int mf = 0; mf < 2; mf++)
        #pragma unroll
        for (int nf = 0; nf < 8; nf++)
            #pragma unroll
            for (int r = 0; r < 4; r++) d[mf][nf][r] = 0.f;

    #pragma unroll
    for (int s = 0; s < 2; s++) {
        const int k0 = s * 32;
        #pragma unroll
        for (int i = 0; i < 2; i++)
            cp16(aBase + s * ABUF + lso[i], Ag + lgi[i] + k0);
        cp_commit();
    }

    int buf = 0;
    for (int it = 0; it < 8; it++) {
        cp_wait1();
        __syncthreads();
        if (it + 2 < 8) {
            int nb = buf + 2; if (nb >= 3) nb -= 3;
            const int k0 = (it + 2) * 32;
            #pragma unroll
            for (int i = 0; i < 2; i++)
                cp16(aBase + (uint32_t)nb * ABUF + lso[i], Ag + lgi[i] + k0);
        }
        cp_commit();
        const uint32_t ab = aBase + (uint32_t)buf * ABUF;
        #pragma unroll
        for (int ks = 0; ks < 2; ks++) {
            const int kslot = it * 2 + ks;       // 0..15: 32B column chunk of B
            uint32_t rb[8][2];
            #pragma unroll
            for (int nf2 = 0; nf2 < 4; nf2++) {
                uint32_t r0, r1, r2, r3;
                const uint32_t addr = bBase + (uint32_t)(bRowL + nf2 * 16) * 528
                                    + kslot * 32 + bCol16;
                ldmatrix_x4(r0, r1, r2, r3, addr);
                rb[nf2 * 2][0] = r0;     rb[nf2 * 2][1] = r1;
                rb[nf2 * 2 + 1][0] = r2; rb[nf2 * 2 + 1][1] = r3;
            }
            uint32_t ra[2][4];
            #pragma unroll
            for (int mf = 0; mf < 2; mf++) {
                const uint32_t addr = ab + (uint32_t)(aRowL + mf * 16) * 80 + ks * 32 + aCol16;
                ldmatrix_x4(ra[mf][0], ra[mf][1], ra[mf][2], ra[mf][3], addr);
            }
            #pragma unroll
            for (int mf = 0; mf < 2; mf++)
                #pragma unroll
                for (int nf = 0; nf < 8; nf++)
                    mma_f16(d[mf][nf], ra[mf], rb[nf]);
        }
        buf++; if (buf == 3) buf = 0;
    }

    const int mBase = warp_m * 32 + (lane >> 2);
    const int nBase = n0 + warp_n * 64 + (lane & 3) * 2;
    if (my == 0) {
        float* outb = g_qkv + (size_t)b * HID * NP;
        #pragma unroll
        for (int mf = 0; mf < 2; mf++) {
            #pragma unroll
            for (int nf = 0; nf < 8; nf++) {
                const int m = mBase + mf * 16;
                const int n = nBase + nf * 8;
                *(float2*)(outb + (size_t)m * NP + n)       = make_float2(d[mf][nf][0], d[mf][nf][1]);
                *(float2*)(outb + (size_t)(m + 8) * NP + n) = make_float2(d[mf][nf][2], d[mf][nf][3]);
            }
        }
    } else {
        const float sc = (my == 2) ? (1.f / 4096.f) : 1.f;
        __half* outb = ((my == 2) ? g_vh : g_kh) + (size_t)b * HID * NP;
        #pragma unroll
        for (int mf = 0; mf < 2; mf++) {
            #pragma unroll
            for (int nf = 0; nf < 8; nf++) {
                const int m = mBase + mf * 16;
                const int n = nBase + nf * 8;
                *(__half2*)(outb + (size_t)m * NP + n) =
                    __floats2half2_rn(d[mf][nf][0] * sc, d[mf][nf][1] * sc);
                *(__half2*)(outb + (size_t)(m + 8) * NP + n) =
                    __floats2half2_rn(d[mf][nf][2] * sc, d[mf][nf][3] * sc);
            }
        }
    }
}

// ---------------------------------------------------------------------------
// K2: per k-row softmax over n=4096 from fp16 g_kh -> fp16 g_keh.
// ---------------------------------------------------------------------------
__global__ __launch_bounds__(256) void k_kstats()
{
    __shared__ float red[256];
    const int row = blockIdx.x;
    const __half* base = g_kh + (size_t)row * NP;
    const int t = threadIdx.x;
    float vals[16];
    #pragma unroll
    for (int j = 0; j < 2; j++) {
        const uint4 raw = *(const uint4*)(base + (j * 256 + t) * 8);
        const __half2* hp = (const __half2*)&raw;
        #pragma unroll
        for (int w = 0; w < 4; w++) {
            const float2 f = __half22float2(hp[w]);
            vals[j * 8 + w * 2]     = f.x;
            vals[j * 8 + w * 2 + 1] = f.y;
        }
    }
    float m = vals[0];
    #pragma unroll
    for (int i = 1; i < 16; i++) m = fmaxf(m, vals[i]);
    red[t] = m; __syncthreads();
    for (int off = 128; off > 0; off >>= 1) {
        if (t < off) red[t] = fmaxf(red[t], red[t + off]);
        __syncthreads();
    }
    m = red[0];
    __syncthreads();
    float e16[16];
    float s = 0.f;
    #pragma unroll
    for (int i = 0; i < 16; i++) { e16[i] = __expf(vals[i] - m); s += e16[i]; }
    red[t] = s; __syncthreads();
    for (int off = 128; off > 0; off >>= 1) {
        if (t < off) red[t] += red[t + off];
        __syncthreads();
    }
    const float inv = 1.f / red[0];
    __half* krow = g_keh + (size_t)row * NP;
    #pragma unroll
    for (int j = 0; j < 2; j++) {
        union { __half h[8]; uint4 u; } pk;
        #pragma unroll
        for (int i = 0; i < 8; i++) pk.h[i] = __float2half(e16[j * 8 + i] * inv);
        *(uint4*)(krow + (j * 256 + t) * 8) = pk.u;
    }
}

// ---------------------------------------------------------------------------
// K3: context = kexp @ vh^T, fp16 HMMA. Grid (4 n-chunks of 1024, 64 z) —
// reverted to the R14 shape (8-chunk split measured slower in R15).
// ---------------------------------------------------------------------------
__global__ __launch_bounds__(256) void k_context()
{
    __shared__ char cxs[34816];
    const uint32_t skB = smem_u32(cxs);
    const uint32_t svB = skB + 17408;
    float* red = (float*)cxs;

    const int ch = blockIdx.x;     // 0..3
    const int z  = blockIdx.y;     // b*4+h
    const int b = z >> 2, h = z & 3;
    const __half* __restrict__ kg = g_keh + ((size_t)b * HID + h * DH) * NP + ch * 1024;
    const __half* __restrict__ vg = g_vh  + ((size_t)b * HID + h * DH) * NP + ch * 1024;

    const int t = threadIdx.x;
    const int wid = t >> 5, lane = t & 31;

    uint32_t lso[4]; uint32_t lgi[4]; bool lk[4];
    #pragma unroll
    for (int i = 0; i < 4; i++) {
        const int slot = t + i * 256;
        const int s = slot & 511;
        const int r = s >> 4, c = s & 15;
        lso[i] = (uint32_t)r * 272 + c * 16;
        lgi[i] = (uint32_t)r * NP + c * 8;
        lk[i] = slot < 512;
    }

    const int aRow = lane & 15;
    const uint32_t aCol16 = (uint32_t)(lane >> 4) * 16;
    const int bg = lane >> 3, blr = lane & 7;
    const int bRow = (bg >> 1) * 8 + blr;
    const uint32_t bCol16 = (uint32_t)(bg & 1) * 16;
    const uint32_t kbyte = (uint32_t)wid * 32;

    float d[2][4][4];
    #pragma unroll
    for (int mf = 0; mf < 2; mf++)
        #pragma unroll
        for (int nf = 0; nf < 4; nf++)
            #pragma unroll
            for (int r = 0; r < 4; r++) d[mf][nf][r] = 0.f;

    #pragma unroll
    for (int i = 0; i < 4; i++)
        cp16((lk[i] ? skB : svB) + lso[i], (lk[i] ? kg : vg) + lgi[i]);
    cp_commit();

    int buf = 0;
    for (int it = 0; it < 8; it++) {
        __syncthreads();
        if (it + 1 < 8) {
            const uint32_t boff = (uint32_t)(buf ^ 1) * 8704;
            const int n0 = (it + 1) * 128;
            #pragma unroll
            for (int i = 0; i < 4; i++)
                cp16((lk[i] ? skB : svB) + boff + lso[i], (lk[i] ? kg : vg) + lgi[i] + n0);
        }
        cp_commit();
        cp_wait1();
        __syncthreads();
        const uint32_t boff = (uint32_t)buf * 8704;
        uint32_t ra[2][4];
        #pragma unroll
        for (int mf = 0; mf < 2; mf++) {
            const uint32_t addr = skB + boff + (uint32_t)(aRow + mf * 16) * 272 + kbyte + aCol16;
            ldmatrix_x4(ra[mf][0], ra[mf][1], ra[mf][2], ra[mf][3], addr);
        }
        uint32_t rb[4][2];
        #pragma unroll
        for (int nf2 = 0; nf2 < 2; nf2++) {
            uint32_t r0, r1, r2, r3;
            const uint32_t addr = svB + boff + (uint32_t)(bRow + nf2 * 16) * 272 + kbyte + bCol16;
            ldmatrix_x4(r0, r1, r2, r3, addr);
            rb[nf2 * 2][0] = r0;     rb[nf2 * 2][1] = r1;
            rb[nf2 * 2 + 1][0] = r2; rb[nf2 * 2 + 1][1] = r3;
        }
        #pragma unroll
        for (int mf = 0; mf < 2; mf++)
            #pragma unroll
            for (int nf = 0; nf < 4; nf++)
                mma_f16(d[mf][nf], ra[mf], rb[nf]);
        buf ^= 1;
    }
    __syncthreads();

    #pragma unroll
    for (int mf = 0; mf < 2; mf++) {
        #pragma unroll
        for (int nf = 0; nf < 4; nf++) {
            const int m = mf * 16 + (lane >> 2);
            const int n = nf * 8 + (lane & 3) * 2;
            red[wid * 1024 + m * 32 + n]           = d[mf][nf][0];
            red[wid * 1024 + m * 32 + n + 1]       = d[mf][nf][1];
            red[wid * 1024 + (m + 8) * 32 + n]     = d[mf][nf][2];
            red[wid * 1024 + (m + 8) * 32 + n + 1] = d[mf][nf][3];
        }
    }
    __syncthreads();
    float* o = g_ctxp + ((size_t)ch * 64 + z) * 1024;
    #pragma unroll
    for (int i = 0; i < 4; i++) {
        const int idx = t * 4 + i;
        float s = 0.f;
        #pragma unroll
        for (int w = 0; w < 8; w++) s += red[w * 1024 + idx];
        o[idx] = s;
    }
}

// ---------------------------------------------------------------------------
// K4: FUSED attn + out-conv + LayerNorm (4-chunk ctx reduce inlined).
// ---------------------------------------------------------------------------
__global__ __launch_bounds__(256, 2) void k_attn_out(
    const float* __restrict__ b_out, const float* __restrict__ g, float* __restrict__ out)
{
    __shared__ alignas(128) char smem_raw[83456];
    const uint32_t aBase = smem_u32(smem_raw);
    const uint32_t bBase = aBase + 61440;
    float* sq   = (float*)smem_raw;                 // [128][68]
    float* sctx = (float*)(smem_raw + 34816);       // [4][32][36]
    __half* sbh = (__half*)(smem_raw + 61440);      // [64][136]
    float* ys   = (float*)smem_raw;                 // [256][66]
    float* redS = (float*)(smem_raw + 78848);
    float* redQ = (float*)(smem_raw + 80896);
    float* smu  = (float*)(smem_raw + 82944);
    float* srs  = (float*)(smem_raw + 83200);

    const int t  = threadIdx.x;
    const int p0 = blockIdx.x * 64;
    const int b  = blockIdx.y;

    {
        const float* qb = g_qkv + (size_t)b * HID * NP;
        const int row = t >> 1, hf = (t & 1) * 32;
        #pragma unroll
        for (int j = 0; j < 8; j++) {
            const float4 v = *(const float4*)(qb + (size_t)row * NP + p0 + hf + j * 4);
            const int c = hf + j * 4;
            sq[row * 68 + c] = v.x; sq[row * 68 + c + 1] = v.y;
            sq[row * 68 + c + 2] = v.z; sq[row * 68 + c + 3] = v.w;
        }
        #pragma unroll
        for (int i = 0; i < 16; i++) {
            const int idx = t + i * 256;
            const int h = idx >> 10, ii = idx & 1023;
            const size_t base = (size_t)(b * 4 + h) * 1024 + ii;
            float s = g_ctxp[base] + g_ctxp[65536 + base]
                    + g_ctxp[131072 + base] + g_ctxp[196608 + base];
            sctx[h * 1152 + (ii >> 5) * 36 + (ii & 31)] = s;
        }
    }
    __syncthreads();

    const int h1 = t >> 6, p1 = t & 63;
    {
        float m = -3.402823e38f;
        #pragma unroll
        for (int d = 0; d < 32; d++) m = fmaxf(m, sq[(h1 * 32 + d) * 68 + p1]);
        float s = 0.f;
        #pragma unroll
        for (int d = 0; d < 32; d++) s += __expf(sq[(h1 * 32 + d) * 68 + p1] - m);
        const float inv = 0.17677669529663687f / s;
        #pragma unroll
        for (int d = 0; d < 32; d++)
            sq[(h1 * 32 + d) * 68 + p1] = __expf(sq[(h1 * 32 + d) * 68 + p1] - m) * inv;
    }
    __syncthreads();

    float acc[32];
    #pragma unroll
    for (int i = 0; i < 32; i++) acc[i] = 0.f;
    #pragma unroll
    for (int d = 0; d < 32; d++) {
        const float qv = sq[(h1 * 32 + d) * 68 + p1];
        const float* cr = sctx + h1 * 1152 + d * 36;
        #pragma unroll
        for (int e4 = 0; e4 < 8; e4++) {
            const float4 cv = *(const float4*)(cr + e4 * 4);
            acc[e4 * 4 + 0] += cv.x * qv;
            acc[e4 * 4 + 1] += cv.y * qv;
            acc[e4 * 4 + 2] += cv.z * qv;
            acc[e4 * 4 + 3] += cv.w * qv;
        }
    }
    __syncthreads();

    const uint32_t ABUF = 20480;
    const int a_r = t >> 2, a_ch = t & 3;
    #pragma unroll
    for (int s = 0; s < 2; s++) {
        const int k0 = s * 32;
        #pragma unroll
        for (int i = 0; i < 4; i++) {
            const int row = a_r + i * 64;
            cp16(aBase + (uint32_t)s * ABUF + (uint32_t)row * 80 + a_ch * 16,
                 g_woh + (size_t)row * 128 + k0 + a_ch * 8);
        }
        cp_commit();
    }
    {
        union { __half h[32]; uint4 u[4]; } hb;
        #pragma unroll
        for (int i = 0; i < 32; i++) hb.h[i] = __float2half(acc[i]);
        uint4* dst = (uint4*)(sbh + p1 * 136 + h1 * 32);
        dst[0] = hb.u[0]; dst[1] = hb.u[1]; dst[2] = hb.u[2]; dst[3] = hb.u[3];
    }

    const int wid = t >> 5, lane = t & 31;
    const int warp_m = wid >> 1, warp_n = wid & 1;
    const int aRowL = warp_m * 64 + (lane & 15);
    const uint32_t aCol16 = (uint32_t)(lane >> 4) * 16;
    const int bg = lane >> 3, blr = lane & 7;
    const int bRowL = warp_n * 32 + (bg >> 1) * 8 + blr;
    const uint32_t bCol16 = (uint32_t)(bg & 1) * 16;

    float d[4][4][4];
    #pragma unroll
    for (int mf = 0; mf < 4; mf++)
        #pragma unroll
        for (int nf = 0; nf < 4; nf++)
            #pragma unroll
            for (int r = 0; r < 4; r++) d[mf][nf][r] = 0.f;

    int buf = 0;
    for (int it = 0; it < 4; it++) {
        cp_wait1();
        __syncthreads();
        if (it + 2 < 4) {
            int nb = buf + 2; if (nb >= 3) nb -= 3;
            const int k0 = (it + 2) * 32;
            #pragma unroll
            for (int i = 0; i < 4; i++) {
                const int row = a_r + i * 64;
                cp16(aBase + (uint32_t)nb * ABUF + (uint32_t)row * 80 + a_ch * 16,
                     g_woh + (size_t)row * 128 + k0 + a_ch * 8);
            }
        }
        cp_commit();
        const uint32_t ab = aBase + (uint32_t)buf * ABUF;
        #pragma unroll
        for (int ks = 0; ks < 2; ks++) {
            const int kslot = it * 2 + ks;
            uint32_t rb[4][2];
            #pragma unroll
            for (int nf2 = 0; nf2 < 2; nf2++) {
                uint32_t r0, r1, r2, r3;
                const uint32_t addr = bBase + (uint32_t)(bRowL + nf2 * 16) * 272
                                    + kslot * 32 + bCol16;
                ldmatrix_x4(r0, r1, r2, r3, addr);
                rb[nf2 * 2][0] = r0;     rb[nf2 * 2][1] = r1;
                rb[nf2 * 2 + 1][0] = r2; rb[nf2 * 2 + 1][1] = r3;
            }
            uint32_t ra[4][4];
            #pragma unroll
            for (int mf = 0; mf < 4; mf++) {
                const uint32_t addr = ab + (uint32_t)(aRowL + mf * 16) * 80 + ks * 32 + aCol16;
                ldmatrix_x4(ra[mf][0], ra[mf][1], ra[mf][2], ra[mf][3], addr);
            }
            #pragma unroll
            for (int mf = 0; mf < 4; mf++)
                #pragma unroll
                for (int nf = 0; nf < 4; nf++)
                    mma_f16(d[mf][nf], ra[mf], rb[nf]);
        }
        buf++; if (buf == 3) buf = 0;
    }
    __syncthreads();

    const int mB = warp_m * 64 + (lane >> 2);
    const int nB = warp_n * 32 + (lane & 3) * 2;
    #pragma unroll
    for (int mf = 0; mf < 4; mf++) {
        #pragma unroll
        for (int nf = 0; nf < 4; nf++) {
            const int m = mB + mf * 16;
            const int n = nB + nf * 8;
            const float bo0 = b_out[m], bo1 = b_out[m + 8];
            ys[m * 66 + n]           = d[mf][nf][0] + bo0;
            ys[m * 66 + n + 1]       = d[mf][nf][1] + bo0;
            ys[(m + 8) * 66 + n]     = d[mf][nf][2] + bo1;
            ys[(m + 8) * 66 + n + 1] = d[mf][nf][3] + bo1;
        }
    }
    __syncthreads();
    {
        float s0 = 0.f, q0 = 0.f, s1 = 0.f, q1 = 0.f;
        #pragma unroll
        for (int c = 0; c < 32; c++) {
            const float v0 = ys[(wid * 32 + c) * 66 + lane];
            const float v1 = ys[(wid * 32 + c) * 66 + lane + 32];
            s0 += v0; q0 += v0 * v0;
            s1 += v1; q1 += v1 * v1;
        }
        redS[wid * 64 + lane] = s0;      redQ[wid * 64 + lane] = q0;
        redS[wid * 64 + lane + 32] = s1; redQ[wid * 64 + lane + 32] = q1;
    }
    __syncthreads();
    if (t < 64) {
        float s = 0.f, q = 0.f;
        #pragma unroll
        for (int w = 0; w < 8; w++) { s += redS[w * 64 + t]; q += redQ[w * 64 + t]; }
        const float mu  = s * (1.f / 256.f);
        const float var = q * (1.f / 256.f) - mu * mu;
        smu[t] = mu;
        srs[t] = rsqrtf(var + 1e-5f);
    }
    __syncthreads();
    {
        const int n2 = t & 63;
        const float mu = smu[n2], rs = srs[n2];
        float* ob = out + (size_t)b * C_ * NP + p0 + n2;
        for (int o = t >> 6; o < C_; o += 4) {
            ob[(size_t)o * NP] = (ys[o * 66 + n2] - mu) * rs * g[o];
        }
    }
}

// ---------------------------------------------------------------------------
extern "C" void kernel_launch(void* const* d_in, const int* in_sizes, int n_in,
                              void* d_out, int out_size)
{
    const float* x     = (const float*)d_in[0];
    const float* w_qkv = (const float*)d_in[1];
    const float* w_out = (const float*)d_in[2];
    const float* b_out = (const float*)d_in[3];
    const float* g     = (const float*)d_in[4];
    float* out = (float*)d_out;
    (void)in_sizes; (void)n_in; (void)out_size;

    k_conv_w<<<512, 256>>>(w_qkv, w_out);
    k_qkv_mma<<<dim3(32, 3, 16), 256>>>(x);
    k_kstats<<<2048, 256>>>();
    k_context<<<dim3(4, 64), 256>>>();
    k_attn_out<<<dim3(64, 16), 256>>>(b_out, g, out);
}

// round 17
// speedup vs baseline: 1.1077x; 1.1077x over previous
#include <cuda_runtime.h>
#include <cuda_fp16.h>
#include <cstdint>
#include <cstddef>

// Problem constants
#define B_     16
#define C_     256
#define HID    128
#define NH     4
#define DH     32
#define NP     4096       // 64*64 spatial positions
#define QKV_CH 384

// Scratch (device globals: allocation-free rule)
__device__ float  g_qkv[(size_t)B_ * HID * NP];      // q only, fp32 (33MB)
__device__ float  g_ctxp[4 * 64 * 1024];
__device__ __half g_wh [(size_t)QKV_CH * 256];       // w_qkv fp16 (single-term)
__device__ __half g_woh[(size_t)C_ * 128];           // w_out fp16 (single-term)
__device__ __half g_kh [(size_t)B_ * HID * NP];      // k fp16 (17MB)
__device__ __half g_keh[(size_t)B_ * HID * NP];      // softmax_n(k) fp16 (17MB)
__device__ __half g_vh [(size_t)B_ * HID * NP];      // v/4096 fp16 (17MB)

// ---------------------------------------------------------------------------
// Portable PTX helpers (sm_80+ only — harness lowers via compute_103 (non-'a'))
// ---------------------------------------------------------------------------
__device__ __forceinline__ uint32_t smem_u32(const void* p) {
    uint32_t a;
    asm("{ .reg .u64 t; cvta.to.shared.u64 t, %1; cvt.u32.u64 %0, t; }" : "=r"(a) : "l"(p));
    return a;
}
__device__ __forceinline__ void cp16(uint32_t s, const void* g) {
    asm volatile("cp.async.cg.shared.global [%0], [%1], 16;" :: "r"(s), "l"(g));
}
__device__ __forceinline__ void cp_commit() {
    asm volatile("cp.async.commit_group;" ::: "memory");
}
__device__ __forceinline__ void cp_wait1() {
    asm volatile("cp.async.wait_group 1;" ::: "memory");
}
__device__ __forceinline__ void cp_wait0() {
    asm volatile("cp.async.wait_group 0;" ::: "memory");
}
__device__ __forceinline__ void ldmatrix_x4(uint32_t& r0, uint32_t& r1,
                                            uint32_t& r2, uint32_t& r3, uint32_t addr) {
    asm volatile("ldmatrix.sync.aligned.m8n8.x4.shared.b16 {%0,%1,%2,%3}, [%4];"
                 : "=r"(r0), "=r"(r1), "=r"(r2), "=r"(r3) : "r"(addr));
}
__device__ __forceinline__ void mma_f16(float* d, const uint32_t* a, const uint32_t* b) {
    asm volatile(
        "mma.sync.aligned.m16n8k16.row.col.f32.f16.f16.f32 "
        "{%0,%1,%2,%3}, {%4,%5,%6,%7}, {%8,%9}, {%0,%1,%2,%3};"
        : "+f"(d[0]), "+f"(d[1]), "+f"(d[2]), "+f"(d[3])
        : "r"(a[0]), "r"(a[1]), "r"(a[2]), "r"(a[3]), "r"(b[0]), "r"(b[1]));
}

// ---------------------------------------------------------------------------
// K0: weight conversions only.
// ---------------------------------------------------------------------------
__global__ __launch_bounds__(256) void k_conv_w(
    const float* __restrict__ wq, const float* __restrict__ wo)
{
    const int t = threadIdx.x;
    if (blockIdx.x < 384) {
        const int i = blockIdx.x * 256 + t;
        g_wh[i] = __float2half(wq[i]);
    } else {
        const int i = (blockIdx.x - 384) * 256 + t;
        g_woh[i] = __float2half(wo[i]);
    }
}

// ---------------------------------------------------------------------------
// K1: qkv GEMM with in-kernel x conversion, CONVERT-ONCE / GEMM-3x.
// Grid (32 n-tiles, 16 b). Phase 0: double-buffered transpose-convert of the
// CTA's B tile x[b][0:256][n0:n0+128] fp32 -> resident fp16 smem (128 x 528B).
// Phase 1: loop my in {q,k,v}: 3-stage A-pipelined single-term fp16 GEMM
// against the SAME resident B (fragments/epilogues identical to R16).
// smem: [0,30720) A ring / phase-0 staging (2 x 8448B); [30720,98304) B.
// ---------------------------------------------------------------------------
__global__ __launch_bounds__(256, 2) void k_qkv_mma(const float* __restrict__ x)
{
    __shared__ alignas(128) char S[98304];
    const uint32_t aBase = smem_u32(S);
    const uint32_t bBase = aBase + 30720;

    const int tid  = threadIdx.x;
    const int wid  = tid >> 5, lane = tid & 31;
    const int n0 = blockIdx.x * 128;
    const int b  = blockIdx.y;
    const int warp_m = wid >> 1, warp_n = wid & 1;

    // ---- Phase 0: convert B tile, 16 double-buffered rounds of 16 channels ----
    {
        const float* xb = x + (size_t)b * C_ * NP + n0;
        const int l_row = tid >> 5;          // 0..7 (+8): staging c-row within round
        const int l_ch  = tid & 31;          // 16B chunk along p
        const int p    = tid >> 1;           // converter: position 0..127
        const int half = (tid & 1) * 8;      // 8-channel half of the 16-ch round

        // prologue: round 0 -> stage 0
        #pragma unroll
        for (int i = 0; i < 2; i++) {
            const int row = l_row + i * 8;   // 0..15
            cp16(aBase + (uint32_t)row * 528 + l_ch * 16,
                 xb + (size_t)row * NP + l_ch * 4);
        }
        cp_commit();

        for (int r = 0; r < 16; r++) {
            if (r + 1 < 16) {
                const uint32_t sb = (uint32_t)((r + 1) & 1) * 8448;
                const int c0n = (r + 1) * 16;
                #pragma unroll
                for (int i = 0; i < 2; i++) {
                    const int row = l_row + i * 8;
                    cp16(aBase + sb + (uint32_t)row * 528 + l_ch * 16,
                         xb + (size_t)(c0n + row) * NP + l_ch * 4);
                }
            }
            cp_commit();
            if (r + 1 < 16) cp_wait1(); else cp_wait0();
            __syncthreads();
            const float* stg = (const float*)(S + (r & 1) * 8448);
            const int c0 = r * 16;
            union { __half h[8]; uint4 u; } hb;
            #pragma unroll
            for (int j = 0; j < 8; j++)
                hb.h[j] = __float2half(stg[(half + j) * 132 + p]);
            *(uint4*)(S + 30720 + (uint32_t)p * 528 + (c0 + half) * 2) = hb.u;
            __syncthreads();
        }
    }

    // ---- Phase 1: three GEMM passes against resident B ----
    const uint32_t ABUF = 128 * 80;   // 10240

    uint32_t lso[2]; uint32_t lgi[2];
    #pragma unroll
    for (int i = 0; i < 2; i++) {
        const int slot = tid + i * 256;
        const int r = slot >> 2, ch = slot & 3;
        lso[i] = (uint32_t)r * 80 + ch * 16;
        lgi[i] = (uint32_t)r * 256 + ch * 8;
    }

    const int aRowL = warp_m * 32 + (lane & 15);
    const uint32_t aCol16 = (uint32_t)(lane >> 4) * 16;
    const int bg = lane >> 3, blr = lane & 7;
    const int bRowL = warp_n * 64 + (bg >> 1) * 8 + blr;
    const uint32_t bCol16 = (uint32_t)(bg & 1) * 16;

    for (int my = 0; my < 3; my++) {
        const __half* __restrict__ Ag = g_wh + (size_t)my * 128 * 256;

        float d[2][8][4];
        #pragma unroll
        for (int mf = 0; mf < 2; mf++)
            #pragma unroll
            for (int nf = 0; nf < 8; nf++)
                #pragma unroll
                for (int r = 0; r < 4; r++) d[mf][nf][r] = 0.f;

        #pragma unroll
        for (int s = 0; s < 2; s++) {
            const int k0 = s * 32;
            #pragma unroll
            for (int i = 0; i < 2; i++)
                cp16(aBase + s * ABUF + lso[i], Ag + lgi[i] + k0);
            cp_commit();
        }

        int buf = 0;
        for (int it = 0; it < 8; it++) {
            cp_wait1();
            __syncthreads();
            if (it + 2 < 8) {
                int nb = buf + 2; if (nb >= 3) nb -= 3;
                const int k0 = (it + 2) * 32;
                #pragma unroll
                for (int i = 0; i < 2; i++)
                    cp16(aBase + (uint32_t)nb * ABUF + lso[i], Ag + lgi[i] + k0);
            }
            cp_commit();
            const uint32_t ab = aBase + (uint32_t)buf * ABUF;
            #pragma unroll
            for (int ks = 0; ks < 2; ks++) {
                const int kslot = it * 2 + ks;       // 0..15 column chunk of B
                uint32_t rb[8][2];
                #pragma unroll
                for (int nf2 = 0; nf2 < 4; nf2++) {
                    uint32_t r0, r1, r2, r3;
                    const uint32_t addr = bBase + (uint32_t)(bRowL + nf2 * 16) * 528
                                        + kslot * 32 + bCol16;
                    ldmatrix_x4(r0, r1, r2, r3, addr);
                    rb[nf2 * 2][0] = r0;     rb[nf2 * 2][1] = r1;
                    rb[nf2 * 2 + 1][0] = r2; rb[nf2 * 2 + 1][1] = r3;
                }
                uint32_t ra[2][4];
                #pragma unroll
                for (int mf = 0; mf < 2; mf++) {
                    const uint32_t addr = ab + (uint32_t)(aRowL + mf * 16) * 80
                                        + ks * 32 + aCol16;
                    ldmatrix_x4(ra[mf][0], ra[mf][1], ra[mf][2], ra[mf][3], addr);
                }
                #pragma unroll
                for (int mf = 0; mf < 2; mf++)
                    #pragma unroll
                    for (int nf = 0; nf < 8; nf++)
                        mma_f16(d[mf][nf], ra[mf], rb[nf]);
            }
            buf++; if (buf == 3) buf = 0;
        }

        const int mBase = warp_m * 32 + (lane >> 2);
        const int nBase = n0 + warp_n * 64 + (lane & 3) * 2;
        if (my == 0) {
            float* outb = g_qkv + (size_t)b * HID * NP;
            #pragma unroll
            for (int mf = 0; mf < 2; mf++) {
                #pragma unroll
                for (int nf = 0; nf < 8; nf++) {
                    const int m = mBase + mf * 16;
                    const int n = nBase + nf * 8;
                    *(float2*)(outb + (size_t)m * NP + n)       = make_float2(d[mf][nf][0], d[mf][nf][1]);
                    *(float2*)(outb + (size_t)(m + 8) * NP + n) = make_float2(d[mf][nf][2], d[mf][nf][3]);
                }
            }
        } else {
            const float sc = (my == 2) ? (1.f / 4096.f) : 1.f;
            __half* outb = ((my == 2) ? g_vh : g_kh) + (size_t)b * HID * NP;
            #pragma unroll
            for (int mf = 0; mf < 2; mf++) {
                #pragma unroll
                for (int nf = 0; nf < 8; nf++) {
                    const int m = mBase + mf * 16;
                    const int n = nBase + nf * 8;
                    *(__half2*)(outb + (size_t)m * NP + n) =
                        __floats2half2_rn(d[mf][nf][0] * sc, d[mf][nf][1] * sc);
                    *(__half2*)(outb + (size_t)(m + 8) * NP + n) =
                        __floats2half2_rn(d[mf][nf][2] * sc, d[mf][nf][3] * sc);
                }
            }
        }
        __syncthreads();   // pass done before next pass reuses the A ring
    }
}

// ---------------------------------------------------------------------------
// K2: per k-row softmax over n=4096 from fp16 g_kh -> fp16 g_keh.
// ---------------------------------------------------------------------------
__global__ __launch_bounds__(256) void k_kstats()
{
    __shared__ float red[256];
    const int row = blockIdx.x;
    const __half* base = g_kh + (size_t)row * NP;
    const int t = threadIdx.x;
    float vals[16];
    #pragma unroll
    for (int j = 0; j < 2; j++) {
        const uint4 raw = *(const uint4*)(base + (j * 256 + t) * 8);
        const __half2* hp = (const __half2*)&raw;
        #pragma unroll
        for (int w = 0; w < 4; w++) {
            const float2 f = __half22float2(hp[w]);
            vals[j * 8 + w * 2]     = f.x;
            vals[j * 8 + w * 2 + 1] = f.y;
        }
    }
    float m = vals[0];
    #pragma unroll
    for (int i = 1; i < 16; i++) m = fmaxf(m, vals[i]);
    red[t] = m; __syncthreads();
    for (int off = 128; off > 0; off >>= 1) {
        if (t < off) red[t] = fmaxf(red[t], red[t + off]);
        __syncthreads();
    }
    m = red[0];
    __syncthreads();
    float e16[16];
    float s = 0.f;
    #pragma unroll
    for (int i = 0; i < 16; i++) { e16[i] = __expf(vals[i] - m); s += e16[i]; }
    red[t] = s; __syncthreads();
    for (int off = 128; off > 0; off >>= 1) {
        if (t < off) red[t] += red[t + off];
        __syncthreads();
    }
    const float inv = 1.f / red[0];
    __half* krow = g_keh + (size_t)row * NP;
    #pragma unroll
    for (int j = 0; j < 2; j++) {
        union { __half h[8]; uint4 u; } pk;
        #pragma unroll
        for (int i = 0; i < 8; i++) pk.h[i] = __float2half(e16[j * 8 + i] * inv);
        *(uint4*)(krow + (j * 256 + t) * 8) = pk.u;
    }
}

// ---------------------------------------------------------------------------
// K3: context = kexp @ vh^T, fp16 HMMA. Grid (4 n-chunks of 1024, 64 z).
// ---------------------------------------------------------------------------
__global__ __launch_bounds__(256) void k_context()
{
    __shared__ char cxs[34816];
    const uint32_t skB = smem_u32(cxs);
    const uint32_t svB = skB + 17408;
    float* red = (float*)cxs;

    const int ch = blockIdx.x;     // 0..3
    const int z  = blockIdx.y;     // b*4+h
    const int b = z >> 2, h = z & 3;
    const __half* __restrict__ kg = g_keh + ((size_t)b * HID + h * DH) * NP + ch * 1024;
    const __half* __restrict__ vg = g_vh  + ((size_t)b * HID + h * DH) * NP + ch * 1024;

    const int t = threadIdx.x;
    const int wid = t >> 5, lane = t & 31;

    uint32_t lso[4]; uint32_t lgi[4]; bool lk[4];
    #pragma unroll
    for (int i = 0; i < 4; i++) {
        const int slot = t + i * 256;
        const int s = slot & 511;
        const int r = s >> 4, c = s & 15;
        lso[i] = (uint32_t)r * 272 + c * 16;
        lgi[i] = (uint32_t)r * NP + c * 8;
        lk[i] = slot < 512;
    }

    const int aRow = lane & 15;
    const uint32_t aCol16 = (uint32_t)(lane >> 4) * 16;
    const int bg = lane >> 3, blr = lane & 7;
    const int bRow = (bg >> 1) * 8 + blr;
    const uint32_t bCol16 = (uint32_t)(bg & 1) * 16;
    const uint32_t kbyte = (uint32_t)wid * 32;

    float d[2][4][4];
    #pragma unroll
    for (int mf = 0; mf < 2; mf++)
        #pragma unroll
        for (int nf = 0; nf < 4; nf++)
            #pragma unroll
            for (int r = 0; r < 4; r++) d[mf][nf][r] = 0.f;

    #pragma unroll
    for (int i = 0; i < 4; i++)
        cp16((lk[i] ? skB : svB) + lso[i], (lk[i] ? kg : vg) + lgi[i]);
    cp_commit();

    int buf = 0;
    for (int it = 0; it < 8; it++) {
        __syncthreads();
        if (it + 1 < 8) {
            const uint32_t boff = (uint32_t)(buf ^ 1) * 8704;
            const int n0 = (it + 1) * 128;
            #pragma unroll
            for (int i = 0; i < 4; i++)
                cp16((lk[i] ? skB : svB) + boff + lso[i], (lk[i] ? kg : vg) + lgi[i] + n0);
        }
        cp_commit();
        cp_wait1();
        __syncthreads();
        const uint32_t boff = (uint32_t)buf * 8704;
        uint32_t ra[2][4];
        #pragma unroll
        for (int mf = 0; mf < 2; mf++) {
            const uint32_t addr = skB + boff + (uint32_t)(aRow + mf * 16) * 272 + kbyte + aCol16;
            ldmatrix_x4(ra[mf][0], ra[mf][1], ra[mf][2], ra[mf][3], addr);
        }
        uint32_t rb[4][2];
        #pragma unroll
        for (int nf2 = 0; nf2 < 2; nf2++) {
            uint32_t r0, r1, r2, r3;
            const uint32_t addr = svB + boff + (uint32_t)(bRow + nf2 * 16) * 272 + kbyte + bCol16;
            ldmatrix_x4(r0, r1, r2, r3, addr);
            rb[nf2 * 2][0] = r0;     rb[nf2 * 2][1] = r1;
            rb[nf2 * 2 + 1][0] = r2; rb[nf2 * 2 + 1][1] = r3;
        }
        #pragma unroll
        for (int mf = 0; mf < 2; mf++)
            #pragma unroll
            for (int nf = 0; nf < 4; nf++)
                mma_f16(d[mf][nf], ra[mf], rb[nf]);
        buf ^= 1;
    }
    __syncthreads();

    #pragma unroll
    for (int mf = 0; mf < 2; mf++) {
        #pragma unroll
        for (int nf = 0; nf < 4; nf++) {
            const int m = mf * 16 + (lane >> 2);
            const int n = nf * 8 + (lane & 3) * 2;
            red[wid * 1024 + m * 32 + n]           = d[mf][nf][0];
            red[wid * 1024 + m * 32 + n + 1]       = d[mf][nf][1];
            red[wid * 1024 + (m + 8) * 32 + n]     = d[mf][nf][2];
            red[wid * 1024 + (m + 8) * 32 + n + 1] = d[mf][nf][3];
        }
    }
    __syncthreads();
    float* o = g_ctxp + ((size_t)ch * 64 + z) * 1024;
    #pragma unroll
    for (int i = 0; i < 4; i++) {
        const int idx = t * 4 + i;
        float s = 0.f;
        #pragma unroll
        for (int w = 0; w < 8; w++) s += red[w * 1024 + idx];
        o[idx] = s;
    }
}

// ---------------------------------------------------------------------------
// K4: FUSED attn + out-conv + LayerNorm (4-chunk ctx reduce inlined).
// ---------------------------------------------------------------------------
__global__ __launch_bounds__(256, 2) void k_attn_out(
    const float* __restrict__ b_out, const float* __restrict__ g, float* __restrict__ out)
{
    __shared__ alignas(128) char smem_raw[83456];
    const uint32_t aBase = smem_u32(smem_raw);
    const uint32_t bBase = aBase + 61440;
    float* sq   = (float*)smem_raw;                 // [128][68]
    float* sctx = (float*)(smem_raw + 34816);       // [4][32][36]
    __half* sbh = (__half*)(smem_raw + 61440);      // [64][136]
    float* ys   = (float*)smem_raw;                 // [256][66]
    float* redS = (float*)(smem_raw + 78848);
    float* redQ = (float*)(smem_raw + 80896);
    float* smu  = (float*)(smem_raw + 82944);
    float* srs  = (float*)(smem_raw + 83200);

    const int t  = threadIdx.x;
    const int p0 = blockIdx.x * 64;
    const int b  = blockIdx.y;

    {
        const float* qb = g_qkv + (size_t)b * HID * NP;
        const int row = t >> 1, hf = (t & 1) * 32;
        #pragma unroll
        for (int j = 0; j < 8; j++) {
            const float4 v = *(const float4*)(qb + (size_t)row * NP + p0 + hf + j * 4);
            const int c = hf + j * 4;
            sq[row * 68 + c] = v.x; sq[row * 68 + c + 1] = v.y;
            sq[row * 68 + c + 2] = v.z; sq[row * 68 + c + 3] = v.w;
        }
        #pragma unroll
        for (int i = 0; i < 16; i++) {
            const int idx = t + i * 256;
            const int h = idx >> 10, ii = idx & 1023;
            const size_t base = (size_t)(b * 4 + h) * 1024 + ii;
            float s = g_ctxp[base] + g_ctxp[65536 + base]
                    + g_ctxp[131072 + base] + g_ctxp[196608 + base];
            sctx[h * 1152 + (ii >> 5) * 36 + (ii & 31)] = s;
        }
    }
    __syncthreads();

    const int h1 = t >> 6, p1 = t & 63;
    {
        float m = -3.402823e38f;
        #pragma unroll
        for (int d = 0; d < 32; d++) m = fmaxf(m, sq[(h1 * 32 + d) * 68 + p1]);
        float s = 0.f;
        #pragma unroll
        for (int d = 0; d < 32; d++) s += __expf(sq[(h1 * 32 + d) * 68 + p1] - m);
        const float inv = 0.17677669529663687f / s;
        #pragma unroll
        for (int d = 0; d < 32; d++)
            sq[(h1 * 32 + d) * 68 + p1] = __expf(sq[(h1 * 32 + d) * 68 + p1] - m) * inv;
    }
    __syncthreads();

    float acc[32];
    #pragma unroll
    for (int i = 0; i < 32; i++) acc[i] = 0.f;
    #pragma unroll
    for (int d = 0; d < 32; d++) {
        const float qv = sq[(h1 * 32 + d) * 68 + p1];
        const float* cr = sctx + h1 * 1152 + d * 36;
        #pragma unroll
        for (int e4 = 0; e4 < 8; e4++) {
            const float4 cv = *(const float4*)(cr + e4 * 4);
            acc[e4 * 4 + 0] += cv.x * qv;
            acc[e4 * 4 + 1] += cv.y * qv;
            acc[e4 * 4 + 2] += cv.z * qv;
            acc[e4 * 4 + 3] += cv.w * qv;
        }
    }
    __syncthreads();

    const uint32_t ABUF = 20480;
    const int a_r = t >> 2, a_ch = t & 3;
    #pragma unroll
    for (int s = 0; s < 2; s++) {
        const int k0 = s * 32;
        #pragma unroll
        for (int i = 0; i < 4; i++) {
            const int row = a_r + i * 64;
            cp16(aBase + (uint32_t)s * ABUF + (uint32_t)row * 80 + a_ch * 16,
                 g_woh + (size_t)row * 128 + k0 + a_ch * 8);
        }
        cp_commit();
    }
    {
        union { __half h[32]; uint4 u[4]; } hb;
        #pragma unroll
        for (int i = 0; i < 32; i++) hb.h[i] = __float2half(acc[i]);
        uint4* dst = (uint4*)(sbh + p1 * 136 + h1 * 32);
        dst[0] = hb.u[0]; dst[1] = hb.u[1]; dst[2] = hb.u[2]; dst[3] = hb.u[3];
    }

    const int wid = t >> 5, lane = t & 31;
    const int warp_m = wid >> 1, warp_n = wid & 1;
    const int aRowL = warp_m * 64 + (lane & 15);
    const uint32_t aCol16 = (uint32_t)(lane >> 4) * 16;
    const int bg = lane >> 3, blr = lane & 7;
    const int bRowL = warp_n * 32 + (bg >> 1) * 8 + blr;
    const uint32_t bCol16 = (uint32_t)(bg & 1) * 16;

    float d[4][4][4];
    #pragma unroll
    for (int mf = 0; mf < 4; mf++)
        #pragma unroll
        for (int nf = 0; nf < 4; nf++)
            #pragma unroll
            for (int r = 0; r < 4; r++) d[mf][nf][r] = 0.f;

    int buf = 0;
    for (int it = 0; it < 4; it++) {
        cp_wait1();
        __syncthreads();
        if (it + 2 < 4) {
            int nb = buf + 2; if (nb >= 3) nb -= 3;
            const int k0 = (it + 2) * 32;
            #pragma unroll
            for (int i = 0; i < 4; i++) {
                const int row = a_r + i * 64;
                cp16(aBase + (uint32_t)nb * ABUF + (uint32_t)row * 80 + a_ch * 16,
                     g_woh + (size_t)row * 128 + k0 + a_ch * 8);
            }
        }
        cp_commit();
        const uint32_t ab = aBase + (uint32_t)buf * ABUF;
        #pragma unroll
        for (int ks = 0; ks < 2; ks++) {
            const int kslot = it * 2 + ks;
            uint32_t rb[4][2];
            #pragma unroll
            for (int nf2 = 0; nf2 < 2; nf2++) {
                uint32_t r0, r1, r2, r3;
                const uint32_t addr = bBase + (uint32_t)(bRowL + nf2 * 16) * 272
                                    + kslot * 32 + bCol16;
                ldmatrix_x4(r0, r1, r2, r3, addr);
                rb[nf2 * 2][0] = r0;     rb[nf2 * 2][1] = r1;
                rb[nf2 * 2 + 1][0] = r2; rb[nf2 * 2 + 1][1] = r3;
            }
            uint32_t ra[4][4];
            #pragma unroll
            for (int mf = 0; mf < 4; mf++) {
                const uint32_t addr = ab + (uint32_t)(aRowL + mf * 16) * 80 + ks * 32 + aCol16;
                ldmatrix_x4(ra[mf][0], ra[mf][1], ra[mf][2], ra[mf][3], addr);
            }
            #pragma unroll
            for (int mf = 0; mf < 4; mf++)
                #pragma unroll
                for (int nf = 0; nf < 4; nf++)
                    mma_f16(d[mf][nf], ra[mf], rb[nf]);
        }
        buf++; if (buf == 3) buf = 0;
    }
    __syncthreads();

    const int mB = warp_m * 64 + (lane >> 2);
    const int nB = warp_n * 32 + (lane & 3) * 2;
    #pragma unroll
    for (int mf = 0; mf < 4; mf++) {
        #pragma unroll
        for (int nf = 0; nf < 4; nf++) {
            const int m = mB + mf * 16;
            const int n = nB + nf * 8;
            const float bo0 = b_out[m], bo1 = b_out[m + 8];
            ys[m * 66 + n]           = d[mf][nf][0] + bo0;
            ys[m * 66 + n + 1]       = d[mf][nf][1] + bo0;
            ys[(m + 8) * 66 + n]     = d[mf][nf][2] + bo1;
            ys[(m + 8) * 66 + n + 1] = d[mf][nf][3] + bo1;
        }
    }
    __syncthreads();
    {
        float s0 = 0.f, q0 = 0.f, s1 = 0.f, q1 = 0.f;
        #pragma unroll
        for (int c = 0; c < 32; c++) {
            const float v0 = ys[(wid * 32 + c) * 66 + lane];
            const float v1 = ys[(wid * 32 + c) * 66 + lane + 32];
            s0 += v0; q0 += v0 * v0;
            s1 += v1; q1 += v1 * v1;
        }
        redS[wid * 64 + lane] = s0;      redQ[wid * 64 + lane] = q0;
        redS[wid * 64 + lane + 32] = s1; redQ[wid * 64 + lane + 32] = q1;
    }
    __syncthreads();
    if (t < 64) {
        float s = 0.f, q = 0.f;
        #pragma unroll
        for (int w = 0; w < 8; w++) { s += redS[w * 64 + t]; q += redQ[w * 64 + t]; }
        const float mu  = s * (1.f / 256.f);
        const float var = q * (1.f / 256.f) - mu * mu;
        smu[t] = mu;
        srs[t] = rsqrtf(var + 1e-5f);
    }
    __syncthreads();
    {
        const int n2 = t & 63;
        const float mu = smu[n2], rs = srs[n2];
        float* ob = out + (size_t)b * C_ * NP + p0 + n2;
        for (int o = t >> 6; o < C_; o += 4) {
            ob[(size_t)o * NP] = (ys[o * 66 + n2] - mu) * rs * g[o];
        }
    }
}

// ---------------------------------------------------------------------------
extern "C" void kernel_launch(void* const* d_in, const int* in_sizes, int n_in,
                              void* d_out, int out_size)
{
    const float* x     = (const float*)d_in[0];
    const float* w_qkv = (const float*)d_in[1];
    const float* w_out = (const float*)d_in[2];
    const float* b_out = (const float*)d_in[3];
    const float* g     = (const float*)d_in[4];
    float* out = (float*)d_out;
    (void)in_sizes; (void)n_in; (void)out_size;

    k_conv_w<<<512, 256>>>(w_qkv, w_out);
    k_qkv_mma<<<dim3(32, 16), 256>>>(x);
    k_kstats<<<2048, 256>>>();
    k_context<<<dim3(4, 64), 256>>>();
    k_attn_out<<<dim3(64, 16), 256>>>(b_out, g, out);
}